// round 2
// baseline (speedup 1.0000x reference)
#include <cuda_runtime.h>

#define NB     2048
#define NOH    20
#define NOTH   23
#define NC     10
#define SC     200      // NOH*NC
#define EMB    9
#define OUTC   32
#define XSTR   43       // NOH + NOTH
#define HW     2304     // 48*48
#define SLABSZ 73728    // OUTC*HW floats per unique slab

// One fully-fused kernel.
// Grid: (mtile 0..17, c 0..7, bg 0..7), 128 threads.
// Each CTA handles spatial m-tile [mtile*128, mtile*128+128) of residue-class c,
// and stores it for the 32 batches b = c + 8*(bg*32 + u).
//
// Key facts (verified in R1, rel_err 1.5e-7):
//   out[b][o][m] depends on b only through c = b & 7   (8 unique slabs)
//   three 1x1 convs fold into one 32x32 weight + bias
//   slab[c][o][m] = cb[o] + sum_i W[o,i]  * v[256*((c+i)&7)+q, r]      (q=m/9, r=m%9)
//                         + sum_j W[o,9+j]* x[bb_j*43 + 20 + (4j+m)%23] (bb_j=(256c+(2304j+m)/23)&2047)
__global__ void __launch_bounds__(128) k_fused(
    const float* __restrict__ x,
    const float* __restrict__ fc_w, const float* __restrict__ fc_b,
    const float* __restrict__ oh_w, const float* __restrict__ oh_b,
    const float* __restrict__ ot_w, const float* __restrict__ ot_b,
    const float* __restrict__ all_w, const float* __restrict__ all_b,
    float* __restrict__ out)
{
    __shared__ __align__(16) float s_fcw[EMB * SC];   // 7.2 KB
    __shared__ __align__(16) float s_W[OUTC * 32];    // fused 32x32 weight
    __shared__ float s_cb[OUTC];                      // fused bias
    __shared__ float s_v[8][16][EMB];                 // needed embedding rows

    const int t     = threadIdx.x;
    const int mtile = blockIdx.x;   // 0..17
    const int c     = blockIdx.y;   // 0..7
    const int bg    = blockIdx.z;   // 0..7

    // ---- prologue A: stage fc_w in smem ------------------------------------
    for (int i = t; i < EMB * SC; i += 128) s_fcw[i] = fc_w[i];

    // ---- prologue B: fold the three convs into one 32x32 weight + bias -----
    for (int idx = t; idx < OUTC * 32; idx += 128) {
        int o = idx >> 5, i = idx & 31;
        float s = 0.f;
        if (i < EMB) {
            #pragma unroll
            for (int cc = 0; cc < EMB; cc++)
                s += all_w[o * 32 + cc] * oh_w[cc * EMB + i];
        } else {
            int j = i - EMB;
            #pragma unroll
            for (int cc = 0; cc < NOTH; cc++)
                s += all_w[o * 32 + EMB + cc] * ot_w[cc * NOTH + j];
        }
        s_W[idx] = s;
    }
    if (t < OUTC) {
        float cb = all_b[t];
        #pragma unroll
        for (int cc = 0; cc < EMB; cc++)  cb += all_w[t * 32 + cc] * oh_b[cc];
        #pragma unroll
        for (int cc = 0; cc < NOTH; cc++) cb += all_w[t * 32 + EMB + cc] * ot_b[cc];
        s_cb[t] = cb;
    }
    __syncthreads();   // s_fcw ready

    // ---- prologue C: compute the embedding rows this m-tile needs ----------
    const int m0 = mtile * 128;
    const int q0 = m0 / 9;
    const int nq = (m0 + 127) / 9 - q0 + 1;   // 14 or 15

    if (t < 8 * nq) {                          // one thread per (k, ql) row
        int k  = t / nq;
        int ql = t - k * nq;
        int b  = 256 * k + q0 + ql;
        const float* xr = x + b * XSTR;        // 20 contiguous one-hot indices
        float acc[EMB];
        #pragma unroll
        for (int e = 0; e < EMB; e++) acc[e] = fc_b[e];
        #pragma unroll
        for (int j = 0; j < NOH; j++) {
            int id   = (int)xr[j];             // exact small int stored as float
            int base = j * NC + id;
            #pragma unroll
            for (int e = 0; e < EMB; e++) acc[e] += s_fcw[e * SC + base];
        }
        #pragma unroll
        for (int e = 0; e < EMB; e++) s_v[k][ql][e] = acc[e];
    }
    __syncthreads();

    // ---- main: gather g[32], dot with fused W, replicate stores ------------
    const int m  = m0 + t;
    const int q  = m / 9;
    const int r  = m - 9 * q;
    const int ql = q - q0;

    float g[32];
    #pragma unroll
    for (int i = 0; i < 9; i++)
        g[i] = s_v[(c + i) & 7][ql][r];
    #pragma unroll
    for (int j = 0; j < 23; j++) {
        int eo = (4 * j + m) % 23;
        int T  = (2304 * j + m) / 23;
        int bb = (256 * c + T) & 2047;
        g[9 + j] = x[bb * XSTR + NOH + eo];
    }

    // base address: batch component c, spatial m; bg picks the 32-batch group
    float* base = out + (size_t)c * SLABSZ + (size_t)m
                      + (size_t)(8 * (bg * 32)) * SLABSZ;

    #pragma unroll
    for (int o = 0; o < OUTC; o++) {
        const float4* W4 = (const float4*)(s_W + o * 32);
        float s = s_cb[o];
        #pragma unroll
        for (int j4 = 0; j4 < 8; j4++) {
            float4 w = W4[j4];
            s += w.x * g[4 * j4]     + w.y * g[4 * j4 + 1]
               + w.z * g[4 * j4 + 2] + w.w * g[4 * j4 + 3];
        }
        float* po = base + (size_t)o * HW;
        #pragma unroll
        for (int u = 0; u < 32; u++)
            po[(size_t)u * 8 * SLABSZ] = s;   // b = c + 8*(bg*32+u)
    }
}

// ---------------------------------------------------------------------------
extern "C" void kernel_launch(void* const* d_in, const int* in_sizes, int n_in,
                              void* d_out, int out_size) {
    const float* x     = (const float*)d_in[0];
    const float* fc_w  = (const float*)d_in[1];
    const float* fc_b  = (const float*)d_in[2];
    const float* oh_w  = (const float*)d_in[3];
    const float* oh_b  = (const float*)d_in[4];
    const float* ot_w  = (const float*)d_in[5];
    const float* ot_b  = (const float*)d_in[6];
    const float* all_w = (const float*)d_in[7];
    const float* all_b = (const float*)d_in[8];
    float* out = (float*)d_out;

    dim3 grid(18, 8, 8);   // (mtile, c, bg) = 1152 CTAs
    k_fused<<<grid, 128>>>(x, fc_w, fc_b, oh_w, oh_b, ot_w, ot_b,
                           all_w, all_b, out);
}

// round 3
// speedup vs baseline: 1.3471x; 1.3471x over previous
#include <cuda_runtime.h>

#define NB     2048
#define NOH    20
#define NOTH   23
#define NC     10
#define SC     200      // NOH*NC
#define EMB    9
#define OUTC   32
#define XSTR   43       // NOH + NOTH
#define HW     2304     // 48*48
#define SLABSZ 73728    // OUTC*HW floats per unique slab

// Scratch (device globals: allocation-free per harness rules)
__device__ float g_slab[8 * SLABSZ];     // the 8 unique output slabs (2.36 MB)

// ---------------------------------------------------------------------------
// k_prologue: one kernel computes the 8 unique slabs.
// Each CTA redundantly folds the three 1x1 convs into a 32x32 weight (+bias),
// computes the ~120 embedding rows its m-tile needs, then evaluates
//   slab[c][o][m] = cb[o] + sum_i W[o,i]  * v[256*((c+i)&7)+q, r]   (q=m/9,r=m%9)
//                         + sum_j W[o,9+j]* x[bb_j*43+20+(4j+m)%23]
// Grid (18, 8) = 144 CTAs x 128 threads.  (Math verified R1/R2, rel_err 1.4e-7.)
__global__ void __launch_bounds__(128) k_prologue(
    const float* __restrict__ x,
    const float* __restrict__ fc_w, const float* __restrict__ fc_b,
    const float* __restrict__ oh_w, const float* __restrict__ oh_b,
    const float* __restrict__ ot_w, const float* __restrict__ ot_b,
    const float* __restrict__ all_w, const float* __restrict__ all_b)
{
    __shared__ __align__(16) float s_fcw[EMB * SC];   // 7.2 KB
    __shared__ __align__(16) float s_W[OUTC * 32];    // fused weight
    __shared__ float s_cb[OUTC];
    __shared__ float s_v[8][16][EMB];

    const int t     = threadIdx.x;
    const int mtile = blockIdx.x;   // 0..17
    const int c     = blockIdx.y;   // 0..7

    // stage fc_w
    for (int i = t; i < EMB * SC; i += 128) s_fcw[i] = fc_w[i];

    // fold weights
    for (int idx = t; idx < OUTC * 32; idx += 128) {
        int o = idx >> 5, i = idx & 31;
        float s = 0.f;
        if (i < EMB) {
            #pragma unroll
            for (int cc = 0; cc < EMB; cc++)
                s += all_w[o * 32 + cc] * oh_w[cc * EMB + i];
        } else {
            int j = i - EMB;
            #pragma unroll
            for (int cc = 0; cc < NOTH; cc++)
                s += all_w[o * 32 + EMB + cc] * ot_w[cc * NOTH + j];
        }
        s_W[idx] = s;
    }
    if (t < OUTC) {
        float cb = all_b[t];
        #pragma unroll
        for (int cc = 0; cc < EMB; cc++)  cb += all_w[t * 32 + cc] * oh_b[cc];
        #pragma unroll
        for (int cc = 0; cc < NOTH; cc++) cb += all_w[t * 32 + EMB + cc] * ot_b[cc];
        s_cb[t] = cb;
    }
    __syncthreads();

    // embedding rows needed by this m-tile
    const int m0 = mtile * 128;
    const int q0 = m0 / 9;
    const int nq = (m0 + 127) / 9 - q0 + 1;   // 14 or 15

    if (t < 8 * nq) {
        int k  = t / nq;
        int ql = t - k * nq;
        int b  = 256 * k + q0 + ql;
        const float* xr = x + b * XSTR;
        float acc[EMB];
        #pragma unroll
        for (int e = 0; e < EMB; e++) acc[e] = fc_b[e];
        #pragma unroll
        for (int j = 0; j < NOH; j++) {
            int id   = (int)xr[j];
            int base = j * NC + id;
            #pragma unroll
            for (int e = 0; e < EMB; e++) acc[e] += s_fcw[e * SC + base];
        }
        #pragma unroll
        for (int e = 0; e < EMB; e++) s_v[k][ql][e] = acc[e];
    }
    __syncthreads();

    // gather + dot, write slab once
    const int m  = m0 + t;
    const int q  = m / 9;
    const int r  = m - 9 * q;
    const int ql = q - q0;

    float g[32];
    #pragma unroll
    for (int i = 0; i < 9; i++)
        g[i] = s_v[(c + i) & 7][ql][r];
    #pragma unroll
    for (int j = 0; j < 23; j++) {
        int eo = (4 * j + m) % 23;
        int T  = (2304 * j + m) / 23;
        int bb = (256 * c + T) & 2047;
        g[9 + j] = x[bb * XSTR + NOH + eo];
    }

    float* dst = g_slab + (size_t)c * SLABSZ + m;
    #pragma unroll
    for (int o = 0; o < OUTC; o++) {
        const float4* W4 = (const float4*)(s_W + o * 32);
        float s = s_cb[o];
        #pragma unroll
        for (int j4 = 0; j4 < 8; j4++) {
            float4 w = W4[j4];
            s += w.x * g[4 * j4]     + w.y * g[4 * j4 + 1]
               + w.z * g[4 * j4 + 2] + w.w * g[4 * j4 + 3];
        }
        dst[o * HW] = s;
    }
}

// ---------------------------------------------------------------------------
// k_replicate: out[b][.] = slab[b%8][.], 604 MB of pure stores.
// Each CTA stages an 8192-float (32 KB) chunk in registers (read once from L2),
// then stores it for 16 batch indices sharing c = b%8.
// grid = 8 c * 9 chunks * 16 bgroups = 1152 CTAs, 256 threads.
__global__ void __launch_bounds__(256) k_replicate(float* __restrict__ out) {
    int bid = blockIdx.x;
    int c     = bid / 144;             // 0..7
    int rest  = bid % 144;
    int chunk = rest / 16;             // 0..8
    int bg    = rest % 16;             // 0..15
    int t = threadIdx.x;

    size_t chunk_off = (size_t)chunk * 8192;
    const float4* __restrict__ src =
        (const float4*)(g_slab + (size_t)c * SLABSZ + chunk_off);

    float4 r0 = src[0 * 256 + t];
    float4 r1 = src[1 * 256 + t];
    float4 r2 = src[2 * 256 + t];
    float4 r3 = src[3 * 256 + t];
    float4 r4 = src[4 * 256 + t];
    float4 r5 = src[5 * 256 + t];
    float4 r6 = src[6 * 256 + t];
    float4 r7 = src[7 * 256 + t];

#pragma unroll 4
    for (int u = 0; u < 16; u++) {
        int b = c + 8 * (bg * 16 + u);
        float4* __restrict__ dst = (float4*)(out + (size_t)b * SLABSZ + chunk_off);
        dst[0 * 256 + t] = r0;
        dst[1 * 256 + t] = r1;
        dst[2 * 256 + t] = r2;
        dst[3 * 256 + t] = r3;
        dst[4 * 256 + t] = r4;
        dst[5 * 256 + t] = r5;
        dst[6 * 256 + t] = r6;
        dst[7 * 256 + t] = r7;
    }
}

// ---------------------------------------------------------------------------
extern "C" void kernel_launch(void* const* d_in, const int* in_sizes, int n_in,
                              void* d_out, int out_size) {
    const float* x     = (const float*)d_in[0];
    const float* fc_w  = (const float*)d_in[1];
    const float* fc_b  = (const float*)d_in[2];
    const float* oh_w  = (const float*)d_in[3];
    const float* oh_b  = (const float*)d_in[4];
    const float* ot_w  = (const float*)d_in[5];
    const float* ot_b  = (const float*)d_in[6];
    const float* all_w = (const float*)d_in[7];
    const float* all_b = (const float*)d_in[8];
    float* out = (float*)d_out;

    dim3 pgrid(18, 8);
    k_prologue<<<pgrid, 128>>>(x, fc_w, fc_b, oh_w, oh_b, ot_w, ot_b,
                               all_w, all_b);
    k_replicate<<<1152, 256>>>(out);
}

// round 4
// speedup vs baseline: 1.4254x; 1.0581x over previous
#include <cuda_runtime.h>

#define NB     2048
#define NOH    20
#define NOTH   23
#define NC     10
#define SC     200      // NOH*NC
#define EMB    9
#define OUTC   32
#define XSTR   43       // NOH + NOTH
#define HW     2304     // 48*48
#define SLABSZ 73728    // OUTC*HW floats per batch

// Single fully-fused, single-wave kernel.
// Grid (18 mtiles, 8 residue classes) = 144 CTAs x 512 threads (1 CTA/SM).
//
// Verified identities (rel_err ~1.4e-7 in R1-R3):
//   out[b][o][m] depends on b only through c = b & 7
//   the three 1x1 convs fold into one 32x32 weight W + bias cb
//   slab[c][o][m] = cb[o] + sum_i W[o,i]  * v[256*((c+i)&7)+q, r]      (q=m/9, r=m%9)
//                         + sum_j W[o,9+j]* x[bb_j*43 + 20 + (4j+m)%23],
//                           bb_j = (256c + (2304j+m)/23) & 2047
__global__ void __launch_bounds__(512) k_fused(
    const float* __restrict__ x,
    const float* __restrict__ fc_w, const float* __restrict__ fc_b,
    const float* __restrict__ oh_w, const float* __restrict__ oh_b,
    const float* __restrict__ ot_w, const float* __restrict__ ot_b,
    const float* __restrict__ all_w, const float* __restrict__ all_b,
    float* __restrict__ out)
{
    __shared__ __align__(16) float s_fcw[EMB * SC];    // 7.2 KB
    __shared__ __align__(16) float s_W[OUTC * 32];     // fused weight
    __shared__ float s_cb[OUTC];                       // fused bias
    __shared__ float s_v[8][16][EMB];                  // embedding rows this tile needs
    __shared__ __align__(16) float s_out[OUTC * 128];  // 16 KB tile [o][m_local]

    const int t     = threadIdx.x;       // 0..511
    const int mtile = blockIdx.x;        // 0..17
    const int c     = blockIdx.y;        // 0..7

    // ---- stage fc_w --------------------------------------------------------
    for (int i = t; i < EMB * SC; i += 512) s_fcw[i] = fc_w[i];

    // ---- fold the three convs into one 32x32 weight + bias -----------------
    for (int idx = t; idx < OUTC * 32; idx += 512) {
        int o = idx >> 5, i = idx & 31;
        float s = 0.f;
        if (i < EMB) {
            #pragma unroll
            for (int cc = 0; cc < EMB; cc++)
                s += all_w[o * 32 + cc] * oh_w[cc * EMB + i];
        } else {
            int j = i - EMB;
            #pragma unroll
            for (int cc = 0; cc < NOTH; cc++)
                s += all_w[o * 32 + EMB + cc] * ot_w[cc * NOTH + j];
        }
        s_W[idx] = s;
    }
    if (t < OUTC) {
        float cb = all_b[t];
        #pragma unroll
        for (int cc = 0; cc < EMB; cc++)  cb += all_w[t * 32 + cc] * oh_b[cc];
        #pragma unroll
        for (int cc = 0; cc < NOTH; cc++) cb += all_w[t * 32 + EMB + cc] * ot_b[cc];
        s_cb[t] = cb;
    }
    __syncthreads();    // s_fcw ready

    // ---- embedding rows needed by this m-tile ------------------------------
    const int m0 = mtile * 128;
    const int q0 = m0 / 9;
    const int nq = (m0 + 127) / 9 - q0 + 1;   // <= 16

    if (t < 8 * nq) {
        int k  = t / nq;
        int ql = t - k * nq;
        int b  = 256 * k + q0 + ql;
        const float* xr = x + b * XSTR;
        float acc[EMB];
        #pragma unroll
        for (int e = 0; e < EMB; e++) acc[e] = fc_b[e];
        #pragma unroll
        for (int j = 0; j < NOH; j++) {
            int id   = (int)xr[j];
            int base = j * NC + id;
            #pragma unroll
            for (int e = 0; e < EMB; e++) acc[e] += s_fcw[e * SC + base];
        }
        #pragma unroll
        for (int e = 0; e < EMB; e++) s_v[k][ql][e] = acc[e];
    }
    __syncthreads();    // s_W, s_cb, s_v ready

    // ---- compute tile: 512-way parallel. thread -> (m_local = t&127, 8 o's)
    {
        const int ml = t & 127;
        const int og = (t >> 7) * 8;          // first of 8 output channels
        const int m  = m0 + ml;
        const int q  = m / 9;
        const int r  = m - 9 * q;
        const int ql = q - q0;

        float g[32];
        #pragma unroll
        for (int i = 0; i < 9; i++)
            g[i] = s_v[(c + i) & 7][ql][r];
        #pragma unroll
        for (int j = 0; j < 23; j++) {
            int eo = (4 * j + m) % 23;
            int T  = (2304 * j + m) / 23;
            int bb = (256 * c + T) & 2047;
            g[9 + j] = x[bb * XSTR + NOH + eo];
        }

        #pragma unroll
        for (int oo = 0; oo < 8; oo++) {
            int o = og + oo;
            const float4* W4 = (const float4*)(s_W + o * 32);
            float s = s_cb[o];
            #pragma unroll
            for (int j4 = 0; j4 < 8; j4++) {
                float4 w = W4[j4];
                s += w.x * g[4 * j4]     + w.y * g[4 * j4 + 1]
                   + w.z * g[4 * j4 + 2] + w.w * g[4 * j4 + 3];
            }
            s_out[o * 128 + ml] = s;
        }
    }
    __syncthreads();    // tile ready

    // ---- store phase: register-staged float4, 512B contiguous per warp ----
    // tile = 1024 float4; thread stages f0 = t, f1 = t + 512.
    const float4* tile4 = (const float4*)s_out;
    float4 r0 = tile4[t];
    float4 r1 = tile4[t + 512];

    // float4 index f -> o = f>>5, ml4 = f&31 ; out float4 offset o*(HW/4) + ml4
    const int f0 = t,        f1 = t + 512;
    const size_t off0 = (size_t)(f0 >> 5) * (HW / 4) + (f0 & 31);
    const size_t off1 = (size_t)(f1 >> 5) * (HW / 4) + (f1 & 31);

    float4* __restrict__ out4 =
        (float4*)(out) + (size_t)(m0 / 4) + (size_t)c * (SLABSZ / 4);

    #pragma unroll 4
    for (int bb = 0; bb < 256; bb++) {
        // b = c + 8*bb ; base float4 offset = b*SLABSZ/4 (c part already added)
        float4* __restrict__ dst = out4 + (size_t)bb * (8 * SLABSZ / 4);
        dst[off0] = r0;
        dst[off1] = r1;
    }
}

// ---------------------------------------------------------------------------
extern "C" void kernel_launch(void* const* d_in, const int* in_sizes, int n_in,
                              void* d_out, int out_size) {
    const float* x     = (const float*)d_in[0];
    const float* fc_w  = (const float*)d_in[1];
    const float* fc_b  = (const float*)d_in[2];
    const float* oh_w  = (const float*)d_in[3];
    const float* oh_b  = (const float*)d_in[4];
    const float* ot_w  = (const float*)d_in[5];
    const float* ot_b  = (const float*)d_in[6];
    const float* all_w = (const float*)d_in[7];
    const float* all_b = (const float*)d_in[8];
    float* out = (float*)d_out;

    dim3 grid(18, 8);   // 144 CTAs, single wave, 1 CTA/SM
    k_fused<<<grid, 512>>>(x, fc_w, fc_b, oh_w, oh_b, ot_w, ot_b,
                           all_w, all_b, out);
}